// round 6
// baseline (speedup 1.0000x reference)
#include <cuda_runtime.h>
#include <math_constants.h>

#define NB 15
#define MAXC 1024
#define L2E 1.4426950408889634f

// Scratch, bin-major: g_conf[b*MAXC + c]. Zero-initialized at load; finalize
// resets everything so graph replays stay correct. No allocation anywhere.
__device__ float g_conf[NB * MAXC];
__device__ float g_lab [NB * MAXC];
__device__ float g_correct[MAXC];
__device__ float g_total  [MAXC];

__device__ __forceinline__ float bnd(int i) {
    return (i >= 15) ? 1.0f : (float)i * (1.0f / 15.0f);
}

// searchsorted(bounds, p, 'left') - 1  for p in (1/15, 1]
__device__ __forceinline__ int bin_of(float p) {
    int k = (int)(p * 15.0f);
    if (k > 14) k = 14;
    if (k < 0)  k = 0;
    while (k > 0  && p <= bnd(k))     k--;
    while (k < 14 && p >  bnd(k + 1)) k++;
    return k;
}

// Monotonic (float,idx) -> u64 key: bigger float wins, ties -> smaller idx.
__device__ __forceinline__ unsigned long long packkey(float m, int idx) {
    unsigned u = __float_as_uint(m);
    u = (u & 0x80000000u) ? ~u : (u | 0x80000000u);
    return ((unsigned long long)u << 32) | (unsigned)(~idx);
}

// Two warps (64 threads) co-own a row pair; each thread owns 16 classes
// (4 float4 segments, col = seg*256 + tp*4). 2 rows per iteration.
// Only a named 64-thread barrier per pair per iteration (double-buffered).
// Grid MUST be <= 444 (3 CTAs/SM x 148 SMs) for a single wave.
__global__ __launch_bounds__(256, 3) void ece_main(
    const float* __restrict__ logits, const int* __restrict__ labels,
    int N, int C)
{
    __shared__ float              s_sum[2][4][2][2];  // [buf][pair][warp][row]
    __shared__ unsigned long long s_key[2][4][2][2];
    __shared__ float              s_conf[MAXC];

    const int tid   = threadIdx.x;
    for (int i = tid; i < MAXC; i += blockDim.x) s_conf[i] = 0.f;
    __syncthreads();

    const int lane  = tid & 31;
    const int pair  = tid >> 6;          // 0..3
    const int pw    = (tid >> 5) & 1;    // warp within pair
    const int tp    = tid & 63;          // thread within pair
    const int pid   = blockIdx.x * 4 + pair;
    const int npair = gridDim.x * 4;
    const int barid = 1 + pair;
    const float B1  = 1.0f / 15.0f;
    const float NEG = -CUDART_INF_F;
    const unsigned FULL = 0xffffffffu;

    float acc[16];
    #pragma unroll
    for (int i = 0; i < 16; i++) acc[i] = 0.f;

    int it = 0;
    for (int r0 = pid * 2; r0 < N; r0 += npair * 2, ++it) {
        const bool has1 = (r0 + 1 < N);
        const float* pa = logits + (size_t)r0 * C;
        const float* pb = logits + (size_t)(has1 ? r0 + 1 : r0) * C;

        float4 ea[4], eb[4];
        float ma = NEG, mb = NEG;
        int   ia = 0x7fffffff, ib = 0x7fffffff;
        float sa = 0.f, sb = 0.f;
        float xa = 0.f, xb = 0.f;          // per-thread max of e (for rare test)

        #pragma unroll
        for (int s = 0; s < 4; s++) {
            const int col = s * 256 + tp * 4;
            float4 va, vb;
            if (col < C) {
                va = *reinterpret_cast<const float4*>(pa + col);
                vb = *reinterpret_cast<const float4*>(pb + col);
            } else {
                va = make_float4(NEG, NEG, NEG, NEG);
                vb = va;
            }
            if (va.x > ma) { ma = va.x; ia = col;     }
            if (va.y > ma) { ma = va.y; ia = col + 1; }
            if (va.z > ma) { ma = va.z; ia = col + 2; }
            if (va.w > ma) { ma = va.w; ia = col + 3; }
            if (vb.x > mb) { mb = vb.x; ib = col;     }
            if (vb.y > mb) { mb = vb.y; ib = col + 1; }
            if (vb.z > mb) { mb = vb.z; ib = col + 2; }
            if (vb.w > mb) { mb = vb.w; ib = col + 3; }
            ea[s].x = exp2f(va.x * L2E); ea[s].y = exp2f(va.y * L2E);
            ea[s].z = exp2f(va.z * L2E); ea[s].w = exp2f(va.w * L2E);
            eb[s].x = exp2f(vb.x * L2E); eb[s].y = exp2f(vb.y * L2E);
            eb[s].z = exp2f(vb.z * L2E); eb[s].w = exp2f(vb.w * L2E);
            sa += (ea[s].x + ea[s].y) + (ea[s].z + ea[s].w);
            sb += (eb[s].x + eb[s].y) + (eb[s].z + eb[s].w);
            xa  = fmaxf(xa, fmaxf(fmaxf(ea[s].x, ea[s].y), fmaxf(ea[s].z, ea[s].w)));
            xb  = fmaxf(xb, fmaxf(fmaxf(eb[s].x, eb[s].y), fmaxf(eb[s].z, eb[s].w)));
        }

        // warp reduce: sums + packed argmax keys
        unsigned long long ka = packkey(ma, ia);
        unsigned long long kb = packkey(mb, ib);
        #pragma unroll
        for (int o = 16; o > 0; o >>= 1) {
            sa += __shfl_xor_sync(FULL, sa, o);
            sb += __shfl_xor_sync(FULL, sb, o);
            unsigned long long oa = __shfl_xor_sync(FULL, ka, o);
            unsigned long long ob = __shfl_xor_sync(FULL, kb, o);
            if (oa > ka) ka = oa;
            if (ob > kb) kb = ob;
        }

        // cross-warp exchange (double-buffered; one named barrier)
        const int buf = it & 1;
        if (lane == 0) {
            s_sum[buf][pair][pw][0] = sa;  s_sum[buf][pair][pw][1] = sb;
            s_key[buf][pair][pw][0] = ka;  s_key[buf][pair][pw][1] = kb;
        }
        asm volatile("bar.sync %0, 64;" :: "r"(barid) : "memory");

        const float suma = s_sum[buf][pair][0][0] + s_sum[buf][pair][1][0];
        const float sumb = s_sum[buf][pair][0][1] + s_sum[buf][pair][1][1];
        const float ra = 1.0f / suma;
        const float rb = has1 ? (1.0f / sumb) : 0.f;

        // per-row bookkeeping: tp==0 -> row a, tp==1 -> row b
        if (tp < 2 && (tp == 0 || has1)) {
            const int   row = r0 + tp;
            const float inv = (tp == 0) ? ra : rb;
            unsigned long long k0 = s_key[buf][pair][0][tp];
            unsigned long long k1 = s_key[buf][pair][1][tp];
            if (k1 > k0) k0 = k1;
            const int argm = (int)(~(unsigned)(k0 & 0xffffffffu));
            const int lab  = labels[row];
            atomicAdd(&g_total[lab], 1.f);
            if (argm == lab) atomicAdd(&g_correct[lab], 1.f);
            const float x = __ldg(logits + (size_t)row * C + lab);  // L1 hit
            const float p = exp2f(x * L2E) * inv;
            if (p > 0.f) {
                const int k = (p > B1) ? bin_of(p) : 0;
                atomicAdd(&g_lab[k * MAXC + lab], 1.f);
            }
        }

        // p-pass: FFMA straight into bin-0 register accumulators
        #pragma unroll
        for (int s = 0; s < 4; s++) {
            acc[s*4+0] = fmaf(ea[s].x, ra, fmaf(eb[s].x, rb, acc[s*4+0]));
            acc[s*4+1] = fmaf(ea[s].y, ra, fmaf(eb[s].y, rb, acc[s*4+1]));
            acc[s*4+2] = fmaf(ea[s].z, ra, fmaf(eb[s].z, rb, acc[s*4+2]));
            acc[s*4+3] = fmaf(ea[s].w, ra, fmaf(eb[s].w, rb, acc[s*4+3]));
        }

        // rare slow path (~1e-6 of elements): move p>1/15 mass to its true bin
        if (fmaxf(xa * ra, xb * rb) > B1) {
            #pragma unroll
            for (int s = 0; s < 4; s++) {
                const int col = s * 256 + tp * 4;
                float pv[8] = { ea[s].x * ra, ea[s].y * ra, ea[s].z * ra, ea[s].w * ra,
                                eb[s].x * rb, eb[s].y * rb, eb[s].z * rb, eb[s].w * rb };
                #pragma unroll
                for (int j = 0; j < 8; j++) {
                    if (pv[j] > B1) {
                        const int c = col + (j & 3);
                        const int k = bin_of(pv[j]);
                        atomicAdd(&g_conf[k * MAXC + c], pv[j]);
                        atomicAdd(&g_conf[c], -pv[j]);   // compensate bin 0
                    }
                }
            }
        }
    }

    // flush: regs -> smem (block combine) -> one atomic/class/block
    #pragma unroll
    for (int s = 0; s < 4; s++) {
        const int col = s * 256 + tp * 4;
        #pragma unroll
        for (int j = 0; j < 4; j++)
            atomicAdd(&s_conf[col + j], acc[s*4+j]);
    }
    __syncthreads();
    for (int c = tid; c < C; c += blockDim.x) {
        const float v = s_conf[c];
        if (v != 0.f) atomicAdd(&g_conf[c], v);          // bin 0, coalesced
    }
}

// Parallel finalize: bin-major layout -> fully coalesced; also resets scratch.
__global__ void finalize_k(float* __restrict__ out, int N, int C) {
    const int c = blockIdx.x * blockDim.x + threadIdx.x;
    if (c >= C) return;
    float s = 0.f;
    #pragma unroll
    for (int b = 0; b < NB; b++) {
        s += fabsf(__ldcg(&g_conf[b * MAXC + c]) - __ldcg(&g_lab[b * MAXC + c]));
        g_conf[b * MAXC + c] = 0.f;
        g_lab [b * MAXC + c] = 0.f;
    }
    out[c]     = s / (float)N;
    out[C + c] = g_correct[c] / g_total[c];
    g_correct[c] = 0.f;
    g_total[c]   = 0.f;
}

extern "C" void kernel_launch(void* const* d_in, const int* in_sizes, int n_in,
                              void* d_out, int out_size) {
    const float* logits = (const float*)d_in[0];
    const int*   labels = (const int*)d_in[1];
    int N = in_sizes[1];
    int C = in_sizes[0] / N;   // 1000; assumes C <= 1024, multiple of 4

    // 148 SMs x 3 CTAs/SM = 444 resident blocks -> exactly one wave.
    ece_main<<<444, 256>>>(logits, labels, N, C);
    finalize_k<<<(C + 127) / 128, 128>>>((float*)d_out, N, C);
}